// round 5
// baseline (speedup 1.0000x reference)
#include <cuda_runtime.h>
#include <math.h>

// Identical grid + grid-stride mapping in BOTH kernels. Pass A reads stripes in
// ascending order (default caching -> the last ~126MB it reads stays in L2).
// Pass B visits stripes in DESCENDING order, so its first reads hit exactly the
// stripes pass A left resident. Within a warp addresses stay ascending
// contiguous 512B; only the (huge, locality-irrelevant) stripe hop reverses.
#define RED_BLOCKS 2368          // 148 SMs * 16 CTAs
#define THREADS 256

__device__ float g_partials[RED_BLOCKS];

__device__ __forceinline__ float block_reduce_max(float m) {
    #pragma unroll
    for (int o = 16; o > 0; o >>= 1)
        m = fmaxf(m, __shfl_xor_sync(0xffffffffu, m, o));
    __shared__ float sm[THREADS / 32];
    int lane = threadIdx.x & 31;
    int w = threadIdx.x >> 5;
    if (lane == 0) sm[w] = m;
    __syncthreads();
    if (w == 0) {
        m = (lane < (THREADS / 32)) ? sm[lane] : 0.0f;
        #pragma unroll
        for (int o = 16; o > 0; o >>= 1)
            m = fmaxf(m, __shfl_xor_sync(0xffffffffu, m, o));
    }
    return m;  // valid in warp 0
}

__device__ __forceinline__ void stcs4(float4* p, float4 v) {
    asm volatile("st.global.cs.v4.f32 [%0], {%1,%2,%3,%4};"
                 :: "l"(p), "f"(v.x), "f"(v.y), "f"(v.z), "f"(v.w) : "memory");
}

__device__ __forceinline__ float max4(float4 v) {
    return fmaxf(fmaxf(fabsf(v.x), fabsf(v.y)), fmaxf(fabsf(v.z), fabsf(v.w)));
}

// Pass A: global max|x|, ascending grid-stride, default-cached loads.
__global__ void __launch_bounds__(THREADS)
bq_max_reduce_kernel(const float4* __restrict__ x, long long nvec,
                     const float* __restrict__ xs, long long ntail_base, int ntail) {
    float m = 0.0f;
    const long long stride = (long long)gridDim.x * THREADS;
    for (long long i = blockIdx.x * (long long)THREADS + threadIdx.x; i < nvec; i += stride)
        m = fmaxf(m, max4(x[i]));

    if (blockIdx.x == 0 && threadIdx.x < (unsigned)ntail)
        m = fmaxf(m, fabsf(xs[ntail_base + threadIdx.x]));

    m = block_reduce_max(m);
    if (threadIdx.x == 0)
        g_partials[blockIdx.x] = m;
}

__device__ __forceinline__ float bq_quant_one(float v, float s, float inv_s) {
    v = (v >= 0.0f) ? fmaxf(v, 1e-10f) : fminf(v, -1e-10f);  // zeros -> +1e-10
    float i = rintf(v * s);                                   // half-to-even
    i = fminf(fmaxf(i, -128.0f), 127.0f);                     // clip to int8 range
    return i * inv_s;                                         // exact pow2 scale
}

__device__ __forceinline__ float4 quant4(float4 v, float s, float inv_s) {
    v.x = bq_quant_one(v.x, s, inv_s);
    v.y = bq_quant_one(v.y, s, inv_s);
    v.z = bq_quant_one(v.z, s, inv_s);
    v.w = bq_quant_one(v.w, s, inv_s);
    return v;
}

// Pass B: prologue reduces partials, then quantize with DESCENDING stripe
// order (same mapping as pass A). x reads default-cached (want L2 hits on the
// hot tail); y stores evict-first so they don't displace it.
__global__ void __launch_bounds__(THREADS)
bq_quantize_kernel(const float4* __restrict__ x, float4* __restrict__ y,
                   long long nvec,
                   const float* __restrict__ xs, float* __restrict__ ys,
                   long long ntail_base, int ntail) {
    __shared__ float s_sc[2];
    {
        float m = 0.0f;
        for (int p = threadIdx.x; p < RED_BLOCKS; p += THREADS)
            m = fmaxf(m, g_partials[p]);
        m = block_reduce_max(m);
        if (threadIdx.x == 0) {
            float maxv = fmaxf(m, 1e-10f);  // the 1e-10 clamp can only raise tiny maxima
            float e = floorf(log2f(maxv));
            e = fminf(fmaxf(e, -128.0f), 127.0f);
            s_sc[0] = exp2f(-e + 6.0f);     // 2^(-e + (bits-2)), bits=8
            s_sc[1] = exp2f(e - 6.0f);
        }
    }
    __syncthreads();
    const float s = s_sc[0], inv_s = s_sc[1];

    const long long stride = (long long)gridDim.x * THREADS;
    const long long i0 = blockIdx.x * (long long)THREADS + threadIdx.x;
    if (i0 < nvec) {
        // start from this thread's highest stripe and walk down
        long long i = i0 + ((nvec - 1 - i0) / stride) * stride;
        for (; i >= i0; i -= stride)
            stcs4(&y[i], quant4(x[i], s, inv_s));
    }

    if (blockIdx.x == 0 && threadIdx.x < (unsigned)ntail)
        ys[ntail_base + threadIdx.x] =
            bq_quant_one(xs[ntail_base + threadIdx.x], s, inv_s);
}

extern "C" void kernel_launch(void* const* d_in, const int* in_sizes, int n_in,
                              void* d_out, int out_size) {
    const float* x = (const float*)d_in[0];
    float* y = (float*)d_out;
    long long n = (long long)in_sizes[0];
    long long nvec = n >> 2;
    long long ntail_base = nvec << 2;
    int ntail = (int)(n - ntail_base);

    bq_max_reduce_kernel<<<RED_BLOCKS, THREADS>>>(
        (const float4*)x, nvec, x, ntail_base, ntail);

    bq_quantize_kernel<<<RED_BLOCKS, THREADS>>>(
        (const float4*)x, (float4*)y, nvec, x, y, ntail_base, ntail);
}